// round 16
// baseline (speedup 1.0000x reference)
#include <cuda_runtime.h>
#include <cstdint>

#define D_MODEL 1024
#define NB 4
#define NCTA 128
#define NTHREADS 256          // 8 warps, one row per warp, 2 units/iteration
#define TP1_MAX 2049
#define BOS 0

typedef unsigned long long u64;

// Tagged hidden state: one 64-bit word per element = {tag:32 | value_bits:32}.
// Producer of h_t stores tag = t+1 in the SAME 8-byte scalar relaxed-atomic
// store as the value (single-copy atomic -> no tearing; proven R8/R15).
// Double-buffered by t&1.
__device__ u64 g_hbuf2[2][NB][D_MODEL];

__global__ void rnn_init_kernel() {
    int i = blockIdx.x * blockDim.x + threadIdx.x;
    if (i < 2 * NB * D_MODEL)
        reinterpret_cast<u64*>(g_hbuf2)[i] = 0ull;   // tag 0 == h_{-1}
}

__device__ __forceinline__ u64 ld_relaxed_u64(const u64* p) {
    u64 v;
    asm volatile("ld.relaxed.gpu.global.u64 %0, [%1];" : "=l"(v) : "l"(p) : "memory");
    return v;
}
__device__ __forceinline__ void st_relaxed_u64(u64* p, u64 v) {
    asm volatile("st.relaxed.gpu.global.u64 [%0], %1;" :: "l"(p), "l"(v) : "memory");
}

// Persistent kernel: 128 CTAs x 8 rows, ONE barrier per PAIR of units.
// Iteration (t, p) computes batches {p, p+2}  (pairing keeps dependency
// distance: iter i+1's inputs were published at iter i-1, so staging at the
// top of iter i has ~1 full iteration of publish->load slack -- unlike R9's
// {b,b+1} pairing which collapsed the slack to sub-iteration).
// Each warp runs TWO independent matvec+reduce chains (ILP hides LDS/SHFL
// latency); the tagged-u64 publish/stage protocol is unchanged from R15.
__global__ void __launch_bounds__(NTHREADS, 1)
rnn_scan_kernel(const int*   __restrict__ ids,
                const float* __restrict__ emb,
                const float* __restrict__ W,
                float*       __restrict__ out,
                int Tp1)
{
    __shared__ unsigned short ids_sm[NB * TP1_MAX];  // tokens incl. BOS
    __shared__ float4 hsm[2][2][D_MODEL / 4];        // [iter parity][unit in pair]

    const int tid  = threadIdx.x;
    const int lane = tid & 31;
    const int w    = tid >> 5;
    const int row  = blockIdx.x * 8 + w;             // this warp's W row

    // ---- W row -> registers: 32 floats/lane (cols 4*(lane + 32k)) ----
    const float4* __restrict__ Wv = reinterpret_cast<const float4*>(W);
    float4 wr[8];
#pragma unroll
    for (int k = 0; k < 8; ++k) wr[k] = Wv[(size_t)row * 256 + lane + 32 * k];

    // ---- stage token ids with BOS prepended ----
    const int T = Tp1 - 1;
    for (int i = tid; i < NB * Tp1; i += NTHREADS) {
        int b = i / Tp1;
        int t = i - b * Tp1;
        ids_sm[i] = (unsigned short)((t == 0) ? BOS : ids[b * T + (t - 1)]);
    }
    {   // inputs of iteration (0,0): h_{-1}(0), h_{-1}(2) = 0
        float4 z = make_float4(0.f, 0.f, 0.f, 0.f);
        hsm[0][0][tid] = z;
        hsm[0][1][tid] = z;
    }
    __syncthreads();

    // ---- embedding prefetch (lane0): statically-indexed per chain ----
    float e_pref[NB];
    if (lane == 0) {
#pragma unroll
        for (int b = 0; b < NB; ++b)
            e_pref[b] = emb[(size_t)ids_sm[b * Tp1] * D_MODEL + row];
    }

    for (int t = 0; t < Tp1; ++t) {
#pragma unroll
        for (int p = 0; p < 2; ++p) {                // iter parity == p
            const int b0 = p, b1 = p + 2;

            // ---- B. stage loads for NEXT iteration's two units ----
            // next iter: (t, 1) if p==0 else (t+1, 0); inputs h_{tn-1}(pn),
            // h_{tn-1}(pn+2) -- published at iteration i-1 (~1 iter slack).
            const int  tn = (p == 0) ? t : t + 1;
            const int  pn = p ^ 1;
            const bool have_next = (tn < Tp1);
            u64 x0, x1, x2, x3, y0, y1, y2, y3;
            const u64* xp = nullptr;
            const u64* yp = nullptr;
            if (have_next) {
                const int slot = (tn + 1) & 1;       // h_{tn-1} lives here
                xp = &g_hbuf2[slot][pn][4 * tid];
                yp = &g_hbuf2[slot][pn + 2][4 * tid];
                x0 = ld_relaxed_u64(xp + 0); x1 = ld_relaxed_u64(xp + 1);
                x2 = ld_relaxed_u64(xp + 2); x3 = ld_relaxed_u64(xp + 3);
                y0 = ld_relaxed_u64(yp + 0); y1 = ld_relaxed_u64(yp + 1);
                y2 = ld_relaxed_u64(yp + 2); y3 = ld_relaxed_u64(yp + 3);
            }

            // ---- C. two independent matvecs (full row per warp each) ----
            const float4* __restrict__ hA = hsm[p][0];
            const float4* __restrict__ hB = hsm[p][1];
            float a0 = 0.f, a1 = 0.f, a2 = 0.f, a3 = 0.f;
            float c0 = 0.f, c1 = 0.f, c2 = 0.f, c3 = 0.f;
#pragma unroll
            for (int kk = 0; kk < 8; kk += 4) {
                float4 u0 = hA[lane + 32 * (kk + 0)];
                float4 u1 = hA[lane + 32 * (kk + 1)];
                float4 u2 = hA[lane + 32 * (kk + 2)];
                float4 u3 = hA[lane + 32 * (kk + 3)];
                float4 v0 = hB[lane + 32 * (kk + 0)];
                float4 v1 = hB[lane + 32 * (kk + 1)];
                float4 v2 = hB[lane + 32 * (kk + 2)];
                float4 v3 = hB[lane + 32 * (kk + 3)];
                a0 += wr[kk + 0].x * u0.x; c0 += wr[kk + 0].x * v0.x;
                a0 += wr[kk + 0].y * u0.y; c0 += wr[kk + 0].y * v0.y;
                a0 += wr[kk + 0].z * u0.z; c0 += wr[kk + 0].z * v0.z;
                a0 += wr[kk + 0].w * u0.w; c0 += wr[kk + 0].w * v0.w;
                a1 += wr[kk + 1].x * u1.x; c1 += wr[kk + 1].x * v1.x;
                a1 += wr[kk + 1].y * u1.y; c1 += wr[kk + 1].y * v1.y;
                a1 += wr[kk + 1].z * u1.z; c1 += wr[kk + 1].z * v1.z;
                a1 += wr[kk + 1].w * u1.w; c1 += wr[kk + 1].w * v1.w;
                a2 += wr[kk + 2].x * u2.x; c2 += wr[kk + 2].x * v2.x;
                a2 += wr[kk + 2].y * u2.y; c2 += wr[kk + 2].y * v2.y;
                a2 += wr[kk + 2].z * u2.z; c2 += wr[kk + 2].z * v2.z;
                a2 += wr[kk + 2].w * u2.w; c2 += wr[kk + 2].w * v2.w;
                a3 += wr[kk + 3].x * u3.x; c3 += wr[kk + 3].x * v3.x;
                a3 += wr[kk + 3].y * u3.y; c3 += wr[kk + 3].y * v3.y;
                a3 += wr[kk + 3].z * u3.z; c3 += wr[kk + 3].z * v3.z;
                a3 += wr[kk + 3].w * u3.w; c3 += wr[kk + 3].w * v3.w;
            }
            float a = (a0 + a1) + (a2 + a3);
            float c = (c0 + c1) + (c2 + c3);
#pragma unroll
            for (int off = 16; off > 0; off >>= 1) {   // interleaved butterflies
                a += __shfl_xor_sync(0xffffffffu, a, off);
                c += __shfl_xor_sync(0xffffffffu, c, off);
            }

            // ---- D. epilogue: publish both h_t values (tagged u64) ----
            if (lane == 0) {
                float va = a + e_pref[b0];
                float vc = c + e_pref[b1];
                const u64 tg = (u64)(unsigned)(t + 1) << 32;
                st_relaxed_u64(&g_hbuf2[t & 1][b0][row], tg | (u64)__float_as_uint(va));
                st_relaxed_u64(&g_hbuf2[t & 1][b1][row], tg | (u64)__float_as_uint(vc));
                out[((size_t)b0 * Tp1 + t) * D_MODEL + row] = va;
                out[((size_t)b1 * Tp1 + t) * D_MODEL + row] = vc;
                if (t + 1 < Tp1) {   // next use is 2 iterations away
                    e_pref[b0] = emb[(size_t)ids_sm[b0 * Tp1 + t + 1] * D_MODEL + row];
                    e_pref[b1] = emb[(size_t)ids_sm[b1 * Tp1 + t + 1] * D_MODEL + row];
                }
            }

            // ---- E. tag checks (loads ~0.8 iteration old) + stash ----
            if (have_next) {
                const unsigned exp = (unsigned)tn;   // tag of h_{tn-1}
                while ((unsigned)(x0 >> 32) != exp || (unsigned)(x1 >> 32) != exp ||
                       (unsigned)(x2 >> 32) != exp || (unsigned)(x3 >> 32) != exp) {
                    x0 = ld_relaxed_u64(xp + 0); x1 = ld_relaxed_u64(xp + 1);
                    x2 = ld_relaxed_u64(xp + 2); x3 = ld_relaxed_u64(xp + 3);
                }
                while ((unsigned)(y0 >> 32) != exp || (unsigned)(y1 >> 32) != exp ||
                       (unsigned)(y2 >> 32) != exp || (unsigned)(y3 >> 32) != exp) {
                    y0 = ld_relaxed_u64(yp + 0); y1 = ld_relaxed_u64(yp + 1);
                    y2 = ld_relaxed_u64(yp + 2); y3 = ld_relaxed_u64(yp + 3);
                }
                hsm[pn][0][tid] = make_float4(__uint_as_float((unsigned)x0),
                                              __uint_as_float((unsigned)x1),
                                              __uint_as_float((unsigned)x2),
                                              __uint_as_float((unsigned)x3));
                hsm[pn][1][tid] = make_float4(__uint_as_float((unsigned)y0),
                                              __uint_as_float((unsigned)y1),
                                              __uint_as_float((unsigned)y2),
                                              __uint_as_float((unsigned)y3));
            }

            // ---- F. single barrier per pair of units ----
            __syncthreads();
        }
    }
}

extern "C" void kernel_launch(void* const* d_in, const int* in_sizes, int n_in,
                              void* d_out, int out_size) {
    const int*   ids = (const int*)d_in[0];
    const float* emb = (const float*)d_in[1];
    const float* W   = (const float*)d_in[2];
    float* out = (float*)d_out;

    int Tp1 = out_size / (NB * D_MODEL);   // 2049 for the reference shapes
    if (Tp1 > TP1_MAX) Tp1 = TP1_MAX;

    rnn_init_kernel<<<32, 256>>>();
    rnn_scan_kernel<<<NCTA, NTHREADS>>>(ids, emb, W, out, Tp1);
}